// round 16
// baseline (speedup 1.0000x reference)
#include <cuda_runtime.h>
#include <cstdint>

#define T_DIM 1024
#define KSZ   64
#define NSZ   64
#define STR   68   // padded W smem stride (one-time fragment LDS, conflict-free)

__device__ __forceinline__ uint32_t f2tf32(float f) {
    uint32_t r; asm("cvt.rna.tf32.f32 %0, %1;" : "=r"(r) : "f"(f)); return r;
}
__device__ __forceinline__ void st_cs_f2(float* p, float v0, float v1) {
    asm volatile("st.global.cs.v2.f32 [%0], {%1, %2};"
                 :: "l"(p), "f"(v0), "f"(v1) : "memory");
}

__global__ __launch_bounds__(256, 2)
void parallel_linear_ldg(const float* __restrict__ x,
                         const float* __restrict__ W,
                         const float* __restrict__ bias,
                         float* __restrict__ out)
{
    __shared__ uint32_t sW[NSZ * STR];
    __shared__ float    sB[NSZ];

    const int t    = blockIdx.x;
    const int tid  = threadIdx.x;
    const int warp = tid >> 5;
    const int lane = tid & 31;
    const int g    = lane >> 2;          // 0..7
    const int tg   = lane & 3;           // 0..3
    const int nhalf = warp & 1;          // 32-col half
    const int mrow  = (warp >> 1) * 16;  // 16-row strip within a 64-row pass

    const size_t rowstride = (size_t)T_DIM * KSZ;

    // ---- stage W_t [64,64] -> tf32 bits in smem (one time) ----
    {
        const float4* Wg = reinterpret_cast<const float4*>(W + (size_t)t * (NSZ * KSZ));
        #pragma unroll
        for (int i = 0; i < 4; i++) {
            int idx = tid + i * 256;
            int n   = idx >> 4;
            int c4  = idx & 15;
            float4 v = Wg[n * 16 + c4];
            uint4 u = make_uint4(f2tf32(v.x), f2tf32(v.y), f2tf32(v.z), f2tf32(v.w));
            *reinterpret_cast<uint4*>(&sW[n * STR + c4 * 4]) = u;
        }
    }
    if (tid < NSZ) sB[tid] = bias[t * NSZ + tid];
    __syncthreads();   // the ONLY barrier

    // ---- W fragments ONCE into registers: 4 n-tiles x 8 ks x 2 = 64 regs ----
    uint32_t wf0[4][8], wf1[4][8];
    #pragma unroll
    for (int nt = 0; nt < 4; nt++) {
        const int ncol = nhalf * 32 + nt * 8 + g;
        #pragma unroll
        for (int ks = 0; ks < 8; ks++) {
            wf0[nt][ks] = sW[ncol * STR + ks * 8 + tg];
            wf1[nt][ks] = sW[ncol * STR + ks * 8 + tg + 4];
        }
    }
    float bb0[4], bb1[4];
    #pragma unroll
    for (int nt = 0; nt < 4; nt++) {
        bb0[nt] = sB[nhalf * 32 + nt * 8 + 2 * tg];
        bb1[nt] = sB[nhalf * 32 + nt * 8 + 2 * tg + 1];
    }

    // ---- 8 free-running passes of 64 rows; A-fragments straight from gmem ----
    #pragma unroll
    for (int p = 0; p < 8; p++) {
        const int rb = p * 64 + mrow;                      // global row of tile top
        const float* xr0 = x + ((size_t)(rb + g) * T_DIM + t) * KSZ;
        const float* xr1 = xr0 + 8 * rowstride;

        float acc[4][4];
        #pragma unroll
        for (int nt = 0; nt < 4; nt++)
            #pragma unroll
            for (int j = 0; j < 4; j++) acc[nt][j] = 0.f;

        #pragma unroll
        for (int h = 0; h < 2; h++) {                      // two K-halves of 32
            // front-batched 16 LDGs (independent -> deep MLP)
            float fa[16];
            #pragma unroll
            for (int ks = 0; ks < 4; ks++) {
                const int k0 = h * 32 + ks * 8;
                fa[ks * 4 + 0] = xr0[k0 + tg];
                fa[ks * 4 + 1] = xr1[k0 + tg];
                fa[ks * 4 + 2] = xr0[k0 + tg + 4];
                fa[ks * 4 + 3] = xr1[k0 + tg + 4];
            }
            #pragma unroll
            for (int ks = 0; ks < 4; ks++) {
                const int kk = h * 4 + ks;
                uint32_t a0 = f2tf32(fa[ks * 4 + 0]);
                uint32_t a1 = f2tf32(fa[ks * 4 + 1]);
                uint32_t a2 = f2tf32(fa[ks * 4 + 2]);
                uint32_t a3 = f2tf32(fa[ks * 4 + 3]);
                #pragma unroll
                for (int nt = 0; nt < 4; nt++) {
                    asm volatile(
                        "mma.sync.aligned.m16n8k8.row.col.f32.tf32.tf32.f32 "
                        "{%0,%1,%2,%3}, {%4,%5,%6,%7}, {%8,%9}, {%0,%1,%2,%3};"
                        : "+f"(acc[nt][0]), "+f"(acc[nt][1]),
                          "+f"(acc[nt][2]), "+f"(acc[nt][3])
                        : "r"(a0), "r"(a1), "r"(a2), "r"(a3),
                          "r"(wf0[nt][kk]), "r"(wf1[nt][kk]));
                }
            }
        }

        // ---- epilogue: +bias, streaming float2 stores (evict-first) ----
        float* o0 = out + ((size_t)(rb + g) * T_DIM + t) * KSZ;
        float* o1 = o0 + 8 * rowstride;
        #pragma unroll
        for (int nt = 0; nt < 4; nt++) {
            const int col = nhalf * 32 + nt * 8 + 2 * tg;
            st_cs_f2(o0 + col, acc[nt][0] + bb0[nt], acc[nt][1] + bb1[nt]);
            st_cs_f2(o1 + col, acc[nt][2] + bb0[nt], acc[nt][3] + bb1[nt]);
        }
    }
}

extern "C" void kernel_launch(void* const* d_in, const int* in_sizes, int n_in,
                              void* d_out, int out_size)
{
    const float* x = (const float*)d_in[0];
    const float* W = (const float*)d_in[1];
    const float* b = (const float*)d_in[2];
    float* out     = (float*)d_out;

    parallel_linear_ldg<<<T_DIM, 256>>>(x, W, b, out);
}